// round 1
// baseline (speedup 1.0000x reference)
#include <cuda_runtime.h>
#include <cuda_bf16.h>
#include <math.h>
#include <float.h>

// Problem constants
#define BATCH    2
#define SEQ      2048
#define MTOK     (BATCH * SEQ)     // 4096 tokens
#define HID      4096
#define NHEADS   32
#define NKV      8
#define HDIM     128
#define KVHID    (NKV * HDIM)      // 1024

// Scratch (allocation-free rule: device globals)
__device__ float g_q[(size_t)MTOK * HID];
__device__ float g_k[(size_t)MTOK * KVHID];
__device__ float g_v[(size_t)MTOK * KVHID];
__device__ float g_attn[(size_t)MTOK * HID];

// ---------------------------------------------------------------------------
// SGEMM: C[M,N] = A[M,K] @ W[N,K]^T   (both row-major), M,N % 128 == 0, K % 8 == 0
// 128x128 block tile, BK=8, 256 threads, 8x8 per thread, float4 fragments.
// ---------------------------------------------------------------------------
__global__ __launch_bounds__(256) void sgemm_nt(
    const float* __restrict__ A, const float* __restrict__ W,
    float* __restrict__ C, int M, int N, int K)
{
    __shared__ float As[8][128];
    __shared__ float Bs[8][128];

    const int tid = threadIdx.x;
    const int bm = blockIdx.y * 128;
    const int bn = blockIdx.x * 128;

    const int lr = tid >> 1;          // 0..127 row within tile
    const int lk = (tid & 1) * 4;     // 0 or 4
    const float* Ap = A + (size_t)(bm + lr) * K + lk;
    const float* Wp = W + (size_t)(bn + lr) * K + lk;

    const int ty = tid >> 4;          // 0..15
    const int tx = tid & 15;          // 0..15

    float acc[8][8];
#pragma unroll
    for (int i = 0; i < 8; i++)
#pragma unroll
        for (int j = 0; j < 8; j++) acc[i][j] = 0.f;

    for (int k0 = 0; k0 < K; k0 += 8) {
        float4 av = *(const float4*)(Ap + k0);
        float4 wv = *(const float4*)(Wp + k0);
        As[lk + 0][lr] = av.x; As[lk + 1][lr] = av.y;
        As[lk + 2][lr] = av.z; As[lk + 3][lr] = av.w;
        Bs[lk + 0][lr] = wv.x; Bs[lk + 1][lr] = wv.y;
        Bs[lk + 2][lr] = wv.z; Bs[lk + 3][lr] = wv.w;
        __syncthreads();

#pragma unroll
        for (int kk = 0; kk < 8; kk++) {
            float4 a0 = *(const float4*)&As[kk][ty * 4];
            float4 a1 = *(const float4*)&As[kk][64 + ty * 4];
            float4 b0 = *(const float4*)&Bs[kk][tx * 4];
            float4 b1 = *(const float4*)&Bs[kk][64 + tx * 4];
            float a[8] = {a0.x, a0.y, a0.z, a0.w, a1.x, a1.y, a1.z, a1.w};
            float b[8] = {b0.x, b0.y, b0.z, b0.w, b1.x, b1.y, b1.z, b1.w};
#pragma unroll
            for (int i = 0; i < 8; i++)
#pragma unroll
                for (int j = 0; j < 8; j++)
                    acc[i][j] = fmaf(a[i], b[j], acc[i][j]);
        }
        __syncthreads();
    }

#pragma unroll
    for (int i = 0; i < 8; i++) {
        int row = bm + ((i < 4) ? (ty * 4 + i) : (64 + ty * 4 + (i - 4)));
        float* Crow = C + (size_t)row * N + bn;
        float4 c0 = make_float4(acc[i][0], acc[i][1], acc[i][2], acc[i][3]);
        float4 c1 = make_float4(acc[i][4], acc[i][5], acc[i][6], acc[i][7]);
        *(float4*)(Crow + tx * 4) = c0;
        *(float4*)(Crow + 64 + tx * 4) = c1;
    }
}

// ---------------------------------------------------------------------------
// RoPE on Q [MTOK, 32*128] and K [MTOK, 8*128], gather-by-position_ids.
// cos/sin computed in double once per (token, freq), applied to all 40 heads.
// rotate_half convention: halves at [0,64) and [64,128).
// ---------------------------------------------------------------------------
__global__ __launch_bounds__(256) void rope_kernel(
    float* __restrict__ Qb, float* __restrict__ Kb, const int* __restrict__ pos)
{
    int idx = blockIdx.x * blockDim.x + threadIdx.x;   // MTOK*64 threads
    int token = idx >> 6;
    int j = idx & 63;
    double inv = exp(((double)(-2 * j) / 128.0) * log(10000.0));
    double ang = (double)pos[token] * inv;
    float c = (float)cos(ang);
    float s = (float)sin(ang);

    float* q = Qb + (size_t)token * HID;
#pragma unroll
    for (int h = 0; h < NHEADS; h++) {
        float x1 = q[h * HDIM + j];
        float x2 = q[h * HDIM + 64 + j];
        q[h * HDIM + j]      = x1 * c - x2 * s;
        q[h * HDIM + 64 + j] = x2 * c + x1 * s;
    }
    float* k = Kb + (size_t)token * KVHID;
#pragma unroll
    for (int h = 0; h < NKV; h++) {
        float x1 = k[h * HDIM + j];
        float x2 = k[h * HDIM + 64 + j];
        k[h * HDIM + j]      = x1 * c - x2 * s;
        k[h * HDIM + 64 + j] = x2 * c + x1 * s;
    }
}

// ---------------------------------------------------------------------------
// Flash attention fp32, causal, GQA (4 q-heads per kv head).
// One block per (q-tile of 64, head, batch). 256 threads.
// Q/K stored d-major (transposed) in smem for conflict-free LDS.128 in S=QK^T.
// Online softmax with per-row (m, l); only the diagonal k-tile is masked.
// Writes O in [token, h*128+d] layout so the output projection is a plain GEMM.
// ---------------------------------------------------------------------------
#define FLASH_SMEM_FLOATS (128*64 + 128*64 + 64*128 + 64*68 + 3*64)

__global__ __launch_bounds__(256) void flash_kernel(
    const float* __restrict__ Q, const float* __restrict__ K,
    const float* __restrict__ V, float* __restrict__ O)
{
    extern __shared__ float sm[];
    float* QsT  = sm;                  // [128][64]  d-major
    float* KsT  = QsT + 128 * 64;      // [128][64]  d-major
    float* Vs   = KsT + 128 * 64;      // [64][128]  row-major
    float* Ps   = Vs + 64 * 128;       // [64][68]   padded
    float* mrow = Ps + 64 * 68;
    float* lrow = mrow + 64;
    float* frow = lrow + 64;

    const int tid = threadIdx.x;
    const int qt = blockIdx.x, h = blockIdx.y, b = blockIdx.z;
    const int q0 = qt * 64;
    const int kvh = h >> 2;
    const float scale = 0.08838834764831845f;  // 1/sqrt(128)

    // Load Q tile (64 x 128) transposed into QsT
    const float* Qbase = Q + ((size_t)b * SEQ + q0) * HID + h * HDIM;
#pragma unroll
    for (int i = 0; i < 8; i++) {
        int lin = tid + 256 * i;          // 0..2047 float4 units
        int r = lin & 63;
        int d = (lin >> 6) * 4;
        float4 v = *(const float4*)(Qbase + (size_t)r * HID + d);
        QsT[(d + 0) * 64 + r] = v.x;
        QsT[(d + 1) * 64 + r] = v.y;
        QsT[(d + 2) * 64 + r] = v.z;
        QsT[(d + 3) * 64 + r] = v.w;
    }
    if (tid < 64) { mrow[tid] = -FLT_MAX; lrow[tid] = 0.f; }

    const int ty = tid >> 4, tx = tid & 15;
    const int r0 = ty * 4;
    const int c0s = tx * 4;
    const int c0o = tx * 8;

    float o[4][8];
#pragma unroll
    for (int i = 0; i < 4; i++)
#pragma unroll
        for (int j = 0; j < 8; j++) o[i][j] = 0.f;

    for (int kt = 0; kt <= qt; kt++) {
        const int k0 = kt * 64;
        __syncthreads();   // previous iteration done with KsT/Vs (and Q load visible)

        const float* Kbase = K + ((size_t)b * SEQ + k0) * KVHID + kvh * HDIM;
        const float* Vbase = V + ((size_t)b * SEQ + k0) * KVHID + kvh * HDIM;
#pragma unroll
        for (int i = 0; i < 8; i++) {
            int lin = tid + 256 * i;
            int r = lin & 63;
            int d = (lin >> 6) * 4;
            float4 kv = *(const float4*)(Kbase + (size_t)r * KVHID + d);
            KsT[(d + 0) * 64 + r] = kv.x;
            KsT[(d + 1) * 64 + r] = kv.y;
            KsT[(d + 2) * 64 + r] = kv.z;
            KsT[(d + 3) * 64 + r] = kv.w;
            int rv = lin >> 5;
            int dv = (lin & 31) * 4;
            float4 vv = *(const float4*)(Vbase + (size_t)rv * KVHID + dv);
            *(float4*)&Vs[rv * 128 + dv] = vv;
        }
        __syncthreads();

        // S tile: 4x4 per thread
        float sacc[4][4];
#pragma unroll
        for (int i = 0; i < 4; i++)
#pragma unroll
            for (int j = 0; j < 4; j++) sacc[i][j] = 0.f;

#pragma unroll 8
        for (int d = 0; d < 128; d++) {
            float4 a  = *(const float4*)&QsT[d * 64 + r0];
            float4 bb = *(const float4*)&KsT[d * 64 + c0s];
            float av[4] = {a.x, a.y, a.z, a.w};
            float bv[4] = {bb.x, bb.y, bb.z, bb.w};
#pragma unroll
            for (int i = 0; i < 4; i++)
#pragma unroll
                for (int j = 0; j < 4; j++)
                    sacc[i][j] = fmaf(av[i], bv[j], sacc[i][j]);
        }

        const bool diag = (kt == qt);
#pragma unroll
        for (int i = 0; i < 4; i++)
#pragma unroll
            for (int j = 0; j < 4; j++) {
                float s = sacc[i][j] * scale;
                if (diag && (k0 + c0s + j > q0 + r0 + i)) s = -FLT_MAX;
                Ps[(r0 + i) * 68 + c0s + j] = s;
            }
        __syncthreads();

        // Online softmax: one thread per row
        if (tid < 64) {
            int r = tid;
            float mold = mrow[r];
            float mx = mold;
#pragma unroll 8
            for (int c = 0; c < 64; c++) mx = fmaxf(mx, Ps[r * 68 + c]);
            float f = __expf(mold - mx);
            float sum = 0.f;
#pragma unroll 8
            for (int c = 0; c < 64; c++) {
                float p = __expf(Ps[r * 68 + c] - mx);
                Ps[r * 68 + c] = p;
                sum += p;
            }
            lrow[r] = lrow[r] * f + sum;
            mrow[r] = mx;
            frow[r] = f;
        }
        __syncthreads();

        // O = O*f + P @ V
        float f[4];
#pragma unroll
        for (int i = 0; i < 4; i++) f[i] = frow[r0 + i];
#pragma unroll
        for (int i = 0; i < 4; i++)
#pragma unroll
            for (int j = 0; j < 8; j++) o[i][j] *= f[i];

#pragma unroll 4
        for (int kk = 0; kk < 64; kk++) {
            float4 v0 = *(const float4*)&Vs[kk * 128 + c0o];
            float4 v1 = *(const float4*)&Vs[kk * 128 + c0o + 4];
            float p[4];
#pragma unroll
            for (int i = 0; i < 4; i++) p[i] = Ps[(r0 + i) * 68 + kk];
#pragma unroll
            for (int i = 0; i < 4; i++) {
                o[i][0] = fmaf(p[i], v0.x, o[i][0]);
                o[i][1] = fmaf(p[i], v0.y, o[i][1]);
                o[i][2] = fmaf(p[i], v0.z, o[i][2]);
                o[i][3] = fmaf(p[i], v0.w, o[i][3]);
                o[i][4] = fmaf(p[i], v1.x, o[i][4]);
                o[i][5] = fmaf(p[i], v1.y, o[i][5]);
                o[i][6] = fmaf(p[i], v1.z, o[i][6]);
                o[i][7] = fmaf(p[i], v1.w, o[i][7]);
            }
        }
    }

    // Epilogue: normalize and store [token, h*128 + d]
    float* Obase = O + ((size_t)b * SEQ + q0) * HID + h * HDIM;
#pragma unroll
    for (int i = 0; i < 4; i++) {
        float linv = 1.f / lrow[r0 + i];
        float4 w0 = make_float4(o[i][0] * linv, o[i][1] * linv, o[i][2] * linv, o[i][3] * linv);
        float4 w1 = make_float4(o[i][4] * linv, o[i][5] * linv, o[i][6] * linv, o[i][7] * linv);
        *(float4*)(Obase + (size_t)(r0 + i) * HID + c0o) = w0;
        *(float4*)(Obase + (size_t)(r0 + i) * HID + c0o + 4) = w1;
    }
}

// ---------------------------------------------------------------------------
// Launch
// ---------------------------------------------------------------------------
extern "C" void kernel_launch(void* const* d_in, const int* in_sizes, int n_in,
                              void* d_out, int out_size)
{
    const float* X   = (const float*)d_in[0];
    const int*   pos = (const int*)d_in[1];
    const float* Wq  = (const float*)d_in[2];
    const float* Wk  = (const float*)d_in[3];
    const float* Wv  = (const float*)d_in[4];
    const float* Wo  = (const float*)d_in[5];
    float* out = (float*)d_out;

    float *q, *k, *v, *attn;
    cudaGetSymbolAddress((void**)&q,    g_q);
    cudaGetSymbolAddress((void**)&k,    g_k);
    cudaGetSymbolAddress((void**)&v,    g_v);
    cudaGetSymbolAddress((void**)&attn, g_attn);

    // Projections
    sgemm_nt<<<dim3(HID / 128, MTOK / 128), 256>>>(X, Wq, q, MTOK, HID, HID);
    sgemm_nt<<<dim3(KVHID / 128, MTOK / 128), 256>>>(X, Wk, k, MTOK, KVHID, HID);
    sgemm_nt<<<dim3(KVHID / 128, MTOK / 128), 256>>>(X, Wv, v, MTOK, KVHID, HID);

    // RoPE on Q and K
    rope_kernel<<<(MTOK * 64) / 256, 256>>>(q, k, pos);

    // Flash attention
    const int flash_smem = FLASH_SMEM_FLOATS * (int)sizeof(float);
    cudaFuncSetAttribute(flash_kernel, cudaFuncAttributeMaxDynamicSharedMemorySize, flash_smem);
    flash_kernel<<<dim3(SEQ / 64, NHEADS, BATCH), 256, flash_smem>>>(q, k, v, attn);

    // Output projection
    sgemm_nt<<<dim3(HID / 128, MTOK / 128), 256>>>(attn, Wo, out, MTOK, HID, HID);
}

// round 4
// speedup vs baseline: 2.0724x; 2.0724x over previous
#include <cuda_runtime.h>
#include <cuda_bf16.h>
#include <math.h>
#include <float.h>
#include <stdint.h>

// Problem constants
#define BATCH    2
#define SEQ      2048
#define MTOK     (BATCH * SEQ)     // 4096 tokens
#define HID      4096
#define NHEADS   32
#define NKV      8
#define HDIM     128
#define KVHID    (NKV * HDIM)      // 1024
#define GK       4096              // K dim of every GEMM here

// ---------------------------------------------------------------------------
// Scratch (allocation-free rule: device globals). uint4 for 16B alignment.
// ---------------------------------------------------------------------------
__device__ float g_q[(size_t)MTOK * HID];
__device__ float g_k[(size_t)MTOK * KVHID];
__device__ float g_v[(size_t)MTOK * KVHID];
__device__ float g_attn[(size_t)MTOK * HID];

#define U4(nbf16) ((nbf16) / 8)
__device__ uint4 g_Xhi [U4((size_t)MTOK * HID)];
__device__ uint4 g_Xlo [U4((size_t)MTOK * HID)];
__device__ uint4 g_Wqhi[U4((size_t)HID * HID)];
__device__ uint4 g_Wqlo[U4((size_t)HID * HID)];
__device__ uint4 g_Wkhi[U4((size_t)KVHID * HID)];
__device__ uint4 g_Wklo[U4((size_t)KVHID * HID)];
__device__ uint4 g_Wvhi[U4((size_t)KVHID * HID)];
__device__ uint4 g_Wvlo[U4((size_t)KVHID * HID)];
__device__ uint4 g_Wohi[U4((size_t)HID * HID)];
__device__ uint4 g_Wolo[U4((size_t)HID * HID)];
__device__ uint4 g_Ahi [U4((size_t)MTOK * HID)];
__device__ uint4 g_Alo [U4((size_t)MTOK * HID)];

// ---------------------------------------------------------------------------
// Split fp32 -> (bf16 hi, bf16 lo).  lo = bf16(x - float(hi)); dropped lo*lo
// term in the GEMM is O(2^-18) relative.
// ---------------------------------------------------------------------------
__global__ __launch_bounds__(256) void split_kernel(
    const float* __restrict__ src, __nv_bfloat16* __restrict__ hi,
    __nv_bfloat16* __restrict__ lo, int n4)   // n4 = n/4
{
    int i = blockIdx.x * blockDim.x + threadIdx.x;
    if (i >= n4) return;
    float4 v = ((const float4*)src)[i];
    __nv_bfloat16 h0 = __float2bfloat16(v.x);
    __nv_bfloat16 h1 = __float2bfloat16(v.y);
    __nv_bfloat16 h2 = __float2bfloat16(v.z);
    __nv_bfloat16 h3 = __float2bfloat16(v.w);
    __nv_bfloat162 H01; H01.x = h0; H01.y = h1;
    __nv_bfloat162 H23; H23.x = h2; H23.y = h3;
    __nv_bfloat162 L01, L23;
    L01.x = __float2bfloat16(v.x - __bfloat162float(h0));
    L01.y = __float2bfloat16(v.y - __bfloat162float(h1));
    L23.x = __float2bfloat16(v.z - __bfloat162float(h2));
    L23.y = __float2bfloat16(v.w - __bfloat162float(h3));
    ((__nv_bfloat162*)hi)[2 * i]     = H01;
    ((__nv_bfloat162*)hi)[2 * i + 1] = H23;
    ((__nv_bfloat162*)lo)[2 * i]     = L01;
    ((__nv_bfloat162*)lo)[2 * i + 1] = L23;
}

// ---------------------------------------------------------------------------
// bf16x3 tensor-core GEMM:  C[M,N] = A[M,K] @ B[N,K]^T  (fp32-accurate)
// Virtual K' = 3K: pass 0 = Ahi*Bhi, pass 1 = Ahi*Blo, pass 2 = Alo*Bhi.
// 128x128 tile, BK=64 bf16, 3-stage cp.async, SW128 swizzle, 8 warps (2m x 4n),
// warp tile 64x32 via mma.sync.m16n8k16.
//
// FRAGMENT NOTE (R3 bug): B smem is [n-row][k-contiguous]; a NON-transposed
// ldmatrix of an 8(n)x8(k) submatrix delivers lane L the pair
// (n = L/4, k = (L%4)*2+{0,1}) packed along k — exactly the mma row.col B
// fragment. The .trans variant (used in R3) packs along n => garbage.
// ---------------------------------------------------------------------------
__device__ __forceinline__ uint32_t swz(uint32_t off) {
    return off ^ ((off >> 3) & 0x70);
}
__device__ __forceinline__ uint32_t smem_u32(const void* p) {
    return (uint32_t)__cvta_generic_to_shared(p);
}
__device__ __forceinline__ void cp16(uint32_t dst, const void* src) {
    asm volatile("cp.async.cg.shared.global [%0], [%1], 16;\n" :: "r"(dst), "l"(src));
}
__device__ __forceinline__ void cp_commit() {
    asm volatile("cp.async.commit_group;\n");
}
__device__ __forceinline__ void cp_wait1() {
    asm volatile("cp.async.wait_group 1;\n");
}
__device__ __forceinline__ void ldsm4(uint32_t r[4], uint32_t addr) {
    asm volatile("ldmatrix.sync.aligned.m8n8.x4.shared.b16 {%0,%1,%2,%3}, [%4];\n"
        : "=r"(r[0]), "=r"(r[1]), "=r"(r[2]), "=r"(r[3]) : "r"(addr));
}
__device__ __forceinline__ void mma16816(float c[4], const uint32_t a[4],
                                         uint32_t b0, uint32_t b1) {
    asm volatile(
        "mma.sync.aligned.m16n8k16.row.col.f32.bf16.bf16.f32 "
        "{%0,%1,%2,%3}, {%4,%5,%6,%7}, {%8,%9}, {%0,%1,%2,%3};\n"
        : "+f"(c[0]), "+f"(c[1]), "+f"(c[2]), "+f"(c[3])
        : "r"(a[0]), "r"(a[1]), "r"(a[2]), "r"(a[3]), "r"(b0), "r"(b1));
}

#define GEMM_STAGES 3
#define TILE_BYTES  (128 * 64 * 2)          // 16KB per operand tile
#define GEMM_SMEM   (GEMM_STAGES * 2 * TILE_BYTES)  // 96KB

__global__ __launch_bounds__(256) void gemm_bf16x3(
    const __nv_bfloat16* __restrict__ Ahi, const __nv_bfloat16* __restrict__ Alo,
    const __nv_bfloat16* __restrict__ Bhi, const __nv_bfloat16* __restrict__ Blo,
    float* __restrict__ C, int N)
{
    extern __shared__ __align__(16) char dsm[];
    const uint32_t aS = smem_u32(dsm);
    const uint32_t bS = aS + GEMM_STAGES * TILE_BYTES;

    const int tid  = threadIdx.x;
    const int lane = tid & 31;
    const int wid  = tid >> 5;
    const int wm   = wid >> 2;          // 0..1
    const int wn   = wid & 3;           // 0..3
    const int bm   = blockIdx.y * 128;
    const int bn   = blockIdx.x * 128;

    const int KCHUNKS = 3 * GK / 64;    // 192

    float acc[4][4][4];
#pragma unroll
    for (int i = 0; i < 4; i++)
#pragma unroll
        for (int j = 0; j < 4; j++)
#pragma unroll
            for (int t = 0; t < 4; t++) acc[i][j][t] = 0.f;

    // precomputed per-thread load indices (r = row in tile, j = 16B unit)
    int lr[4], lj[4];
#pragma unroll
    for (int i = 0; i < 4; i++) {
        int lin = i * 256 + tid;
        lr[i] = lin >> 3;
        lj[i] = lin & 7;
    }

    auto issue_loads = [&](int c, int st) {
        int pass  = c >> 6;             // GK/64 = 64 chunks per pass
        int kreal = (c & 63) << 6;
        const __nv_bfloat16* Asrc = (pass < 2) ? Ahi : Alo;
        const __nv_bfloat16* Bsrc = (pass == 1) ? Blo : Bhi;
#pragma unroll
        for (int i = 0; i < 4; i++) {
            uint32_t off = swz(lr[i] * 128 + lj[i] * 16);
            cp16(aS + st * TILE_BYTES + off,
                 Asrc + (size_t)(bm + lr[i]) * GK + kreal + lj[i] * 8);
            cp16(bS + st * TILE_BYTES + off,
                 Bsrc + (size_t)(bn + lr[i]) * GK + kreal + lj[i] * 8);
        }
    };

    // prologue: stages 0,1
    issue_loads(0, 0); cp_commit();
    issue_loads(1, 1); cp_commit();

    for (int c = 0; c < KCHUNKS; c++) {
        cp_wait1();
        __syncthreads();

        if (c + 2 < KCHUNKS) issue_loads(c + 2, (c + 2) % GEMM_STAGES);
        cp_commit();

        const int st = c % GEMM_STAGES;
        const uint32_t aT = aS + st * TILE_BYTES;
        const uint32_t bT = bS + st * TILE_BYTES;

#pragma unroll
        for (int kk = 0; kk < 64; kk += 16) {
            uint32_t afr[4][4];
            uint32_t bfr[2][4];
#pragma unroll
            for (int mt = 0; mt < 4; mt++) {
                int row = wm * 64 + mt * 16 + (lane & 15);
                uint32_t off = row * 128 + kk * 2 + (lane >> 4) * 16;
                ldsm4(afr[mt], aT + swz(off));
            }
#pragma unroll
            for (int nt2 = 0; nt2 < 2; nt2++) {
                int row = wn * 32 + nt2 * 16 + (lane & 7) + ((lane >> 4) & 1) * 8;
                uint32_t off = row * 128 + kk * 2 + ((lane >> 3) & 1) * 16;
                ldsm4(bfr[nt2], bT + swz(off));   // NON-trans (R3 fix)
            }
#pragma unroll
            for (int mt = 0; mt < 4; mt++)
#pragma unroll
                for (int nt = 0; nt < 4; nt++)
                    mma16816(acc[mt][nt], afr[mt],
                             bfr[nt >> 1][(nt & 1) * 2],
                             bfr[nt >> 1][(nt & 1) * 2 + 1]);
        }
    }

    // epilogue
#pragma unroll
    for (int mt = 0; mt < 4; mt++) {
#pragma unroll
        for (int nt = 0; nt < 4; nt++) {
            int row = bm + wm * 64 + mt * 16 + (lane >> 2);
            int col = bn + wn * 32 + nt * 8 + (lane & 3) * 2;
            float2 v0 = make_float2(acc[mt][nt][0], acc[mt][nt][1]);
            float2 v1 = make_float2(acc[mt][nt][2], acc[mt][nt][3]);
            *(float2*)&C[(size_t)row * N + col] = v0;
            *(float2*)&C[(size_t)(row + 8) * N + col] = v1;
        }
    }
}

// ---------------------------------------------------------------------------
// RoPE on Q [MTOK, 32*128] and K [MTOK, 8*128], gather-by-position_ids.
// ---------------------------------------------------------------------------
__global__ __launch_bounds__(256) void rope_kernel(
    float* __restrict__ Qb, float* __restrict__ Kb, const int* __restrict__ pos)
{
    int idx = blockIdx.x * blockDim.x + threadIdx.x;
    int token = idx >> 6;
    int j = idx & 63;
    double inv = exp(((double)(-2 * j) / 128.0) * log(10000.0));
    double ang = (double)pos[token] * inv;
    float c = (float)cos(ang);
    float s = (float)sin(ang);

    float* q = Qb + (size_t)token * HID;
#pragma unroll
    for (int h = 0; h < NHEADS; h++) {
        float x1 = q[h * HDIM + j];
        float x2 = q[h * HDIM + 64 + j];
        q[h * HDIM + j]      = x1 * c - x2 * s;
        q[h * HDIM + 64 + j] = x2 * c + x1 * s;
    }
    float* k = Kb + (size_t)token * KVHID;
#pragma unroll
    for (int h = 0; h < NKV; h++) {
        float x1 = k[h * HDIM + j];
        float x2 = k[h * HDIM + 64 + j];
        k[h * HDIM + j]      = x1 * c - x2 * s;
        k[h * HDIM + 64 + j] = x2 * c + x1 * s;
    }
}

// ---------------------------------------------------------------------------
// Flash attention fp32, causal, GQA (unchanged — next round's target)
// ---------------------------------------------------------------------------
#define FLASH_SMEM_FLOATS (128*64 + 128*64 + 64*128 + 64*68 + 3*64)

__global__ __launch_bounds__(256) void flash_kernel(
    const float* __restrict__ Q, const float* __restrict__ K,
    const float* __restrict__ V, float* __restrict__ O)
{
    extern __shared__ float sm[];
    float* QsT  = sm;
    float* KsT  = QsT + 128 * 64;
    float* Vs   = KsT + 128 * 64;
    float* Ps   = Vs + 64 * 128;
    float* mrow = Ps + 64 * 68;
    float* lrow = mrow + 64;
    float* frow = lrow + 64;

    const int tid = threadIdx.x;
    const int qt = blockIdx.x, h = blockIdx.y, b = blockIdx.z;
    const int q0 = qt * 64;
    const int kvh = h >> 2;
    const float scale = 0.08838834764831845f;

    const float* Qbase = Q + ((size_t)b * SEQ + q0) * HID + h * HDIM;
#pragma unroll
    for (int i = 0; i < 8; i++) {
        int lin = tid + 256 * i;
        int r = lin & 63;
        int d = (lin >> 6) * 4;
        float4 v = *(const float4*)(Qbase + (size_t)r * HID + d);
        QsT[(d + 0) * 64 + r] = v.x;
        QsT[(d + 1) * 64 + r] = v.y;
        QsT[(d + 2) * 64 + r] = v.z;
        QsT[(d + 3) * 64 + r] = v.w;
    }
    if (tid < 64) { mrow[tid] = -FLT_MAX; lrow[tid] = 0.f; }

    const int ty = tid >> 4, tx = tid & 15;
    const int r0 = ty * 4;
    const int c0s = tx * 4;
    const int c0o = tx * 8;

    float o[4][8];
#pragma unroll
    for (int i = 0; i < 4; i++)
#pragma unroll
        for (int j = 0; j < 8; j++) o[i][j] = 0.f;

    for (int kt = 0; kt <= qt; kt++) {
        const int k0 = kt * 64;
        __syncthreads();

        const float* Kbase = K + ((size_t)b * SEQ + k0) * KVHID + kvh * HDIM;
        const float* Vbase = V + ((size_t)b * SEQ + k0) * KVHID + kvh * HDIM;
#pragma unroll
        for (int i = 0; i < 8; i++) {
            int lin = tid + 256 * i;
            int r = lin & 63;
            int d = (lin >> 6) * 4;
            float4 kv = *(const float4*)(Kbase + (size_t)r * KVHID + d);
            KsT[(d + 0) * 64 + r] = kv.x;
            KsT[(d + 1) * 64 + r] = kv.y;
            KsT[(d + 2) * 64 + r] = kv.z;
            KsT[(d + 3) * 64 + r] = kv.w;
            int rv = lin >> 5;
            int dv = (lin & 31) * 4;
            float4 vv = *(const float4*)(Vbase + (size_t)rv * KVHID + dv);
            *(float4*)&Vs[rv * 128 + dv] = vv;
        }
        __syncthreads();

        float sacc[4][4];
#pragma unroll
        for (int i = 0; i < 4; i++)
#pragma unroll
            for (int j = 0; j < 4; j++) sacc[i][j] = 0.f;

#pragma unroll 8
        for (int d = 0; d < 128; d++) {
            float4 a  = *(const float4*)&QsT[d * 64 + r0];
            float4 bb = *(const float4*)&KsT[d * 64 + c0s];
            float av[4] = {a.x, a.y, a.z, a.w};
            float bv[4] = {bb.x, bb.y, bb.z, bb.w};
#pragma unroll
            for (int i = 0; i < 4; i++)
#pragma unroll
                for (int j = 0; j < 4; j++)
                    sacc[i][j] = fmaf(av[i], bv[j], sacc[i][j]);
        }

        const bool diag = (kt == qt);
#pragma unroll
        for (int i = 0; i < 4; i++)
#pragma unroll
            for (int j = 0; j < 4; j++) {
                float s = sacc[i][j] * scale;
                if (diag && (k0 + c0s + j > q0 + r0 + i)) s = -FLT_MAX;
                Ps[(r0 + i) * 68 + c0s + j] = s;
            }
        __syncthreads();

        if (tid < 64) {
            int r = tid;
            float mold = mrow[r];
            float mx = mold;
#pragma unroll 8
            for (int c = 0; c < 64; c++) mx = fmaxf(mx, Ps[r * 68 + c]);
            float f = __expf(mold - mx);
            float sum = 0.f;
#pragma unroll 8
            for (int c = 0; c < 64; c++) {
                float p = __expf(Ps[r * 68 + c] - mx);
                Ps[r * 68 + c] = p;
                sum += p;
            }
            lrow[r] = lrow[r] * f + sum;
            mrow[r] = mx;
            frow[r] = f;
        }
        __syncthreads();

        float f[4];
#pragma unroll
        for (int i = 0; i < 4; i++) f[i] = frow[r0 + i];
#pragma unroll
        for (int i = 0; i < 4; i++)
#pragma unroll
            for (int j = 0; j < 8; j++) o[i][j] *= f[i];

#pragma unroll 4
        for (int kk = 0; kk < 64; kk++) {
            float4 v0 = *(const float4*)&Vs[kk * 128 + c0o];
            float4 v1 = *(const float4*)&Vs[kk * 128 + c0o + 4];
            float p[4];
#pragma unroll
            for (int i = 0; i < 4; i++) p[i] = Ps[(r0 + i) * 68 + kk];
#pragma unroll
            for (int i = 0; i < 4; i++) {
                o[i][0] = fmaf(p[i], v0.x, o[i][0]);
                o[i][1] = fmaf(p[i], v0.y, o[i][1]);
                o[i][2] = fmaf(p[i], v0.z, o[i][2]);
                o[i][3] = fmaf(p[i], v0.w, o[i][3]);
                o[i][4] = fmaf(p[i], v1.x, o[i][4]);
                o[i][5] = fmaf(p[i], v1.y, o[i][5]);
                o[i][6] = fmaf(p[i], v1.z, o[i][6]);
                o[i][7] = fmaf(p[i], v1.w, o[i][7]);
            }
        }
    }

    float* Obase = O + ((size_t)b * SEQ + q0) * HID + h * HDIM;
#pragma unroll
    for (int i = 0; i < 4; i++) {
        float linv = 1.f / lrow[r0 + i];
        float4 w0 = make_float4(o[i][0] * linv, o[i][1] * linv, o[i][2] * linv, o[i][3] * linv);
        float4 w1 = make_float4(o[i][4] * linv, o[i][5] * linv, o[i][6] * linv, o[i][7] * linv);
        *(float4*)(Obase + (size_t)(r0 + i) * HID + c0o) = w0;
        *(float4*)(Obase + (size_t)(r0 + i) * HID + c0o + 4) = w1;
    }
}

// ---------------------------------------------------------------------------
// Launch
// ---------------------------------------------------------------------------
extern "C" void kernel_launch(void* const* d_in, const int* in_sizes, int n_in,
                              void* d_out, int out_size)
{
    const float* X   = (const float*)d_in[0];
    const int*   pos = (const int*)d_in[1];
    const float* Wq  = (const float*)d_in[2];
    const float* Wk  = (const float*)d_in[3];
    const float* Wv  = (const float*)d_in[4];
    const float* Wo  = (const float*)d_in[5];
    float* out = (float*)d_out;

    float *q, *k, *v, *attn;
    cudaGetSymbolAddress((void**)&q,    g_q);
    cudaGetSymbolAddress((void**)&k,    g_k);
    cudaGetSymbolAddress((void**)&v,    g_v);
    cudaGetSymbolAddress((void**)&attn, g_attn);

    __nv_bfloat16 *Xhi, *Xlo, *Wqhi, *Wqlo, *Wkhi, *Wklo, *Wvhi, *Wvlo, *Wohi, *Wolo, *Ahi, *Alo;
    cudaGetSymbolAddress((void**)&Xhi,  g_Xhi);  cudaGetSymbolAddress((void**)&Xlo,  g_Xlo);
    cudaGetSymbolAddress((void**)&Wqhi, g_Wqhi); cudaGetSymbolAddress((void**)&Wqlo, g_Wqlo);
    cudaGetSymbolAddress((void**)&Wkhi, g_Wkhi); cudaGetSymbolAddress((void**)&Wklo, g_Wklo);
    cudaGetSymbolAddress((void**)&Wvhi, g_Wvhi); cudaGetSymbolAddress((void**)&Wvlo, g_Wvlo);
    cudaGetSymbolAddress((void**)&Wohi, g_Wohi); cudaGetSymbolAddress((void**)&Wolo, g_Wolo);
    cudaGetSymbolAddress((void**)&Ahi,  g_Ahi);  cudaGetSymbolAddress((void**)&Alo,  g_Alo);

    const int n16M = MTOK * HID / 4;   // float4 count for 16M-elem arrays
    const int n4M  = KVHID * HID / 4;

    // Splits
    split_kernel<<<(n16M + 255) / 256, 256>>>(X,  Xhi,  Xlo,  n16M);
    split_kernel<<<(n16M + 255) / 256, 256>>>(Wq, Wqhi, Wqlo, n16M);
    split_kernel<<<(n4M  + 255) / 256, 256>>>(Wk, Wkhi, Wklo, n4M);
    split_kernel<<<(n4M  + 255) / 256, 256>>>(Wv, Wvhi, Wvlo, n4M);
    split_kernel<<<(n16M + 255) / 256, 256>>>(Wo, Wohi, Wolo, n16M);

    // Projections (tensor core, bf16x3)
    cudaFuncSetAttribute(gemm_bf16x3, cudaFuncAttributeMaxDynamicSharedMemorySize, GEMM_SMEM);
    gemm_bf16x3<<<dim3(HID / 128,   MTOK / 128), 256, GEMM_SMEM>>>(Xhi, Xlo, Wqhi, Wqlo, q, HID);
    gemm_bf16x3<<<dim3(KVHID / 128, MTOK / 128), 256, GEMM_SMEM>>>(Xhi, Xlo, Wkhi, Wklo, k, KVHID);
    gemm_bf16x3<<<dim3(KVHID / 128, MTOK / 128), 256, GEMM_SMEM>>>(Xhi, Xlo, Wvhi, Wvlo, v, KVHID);

    // RoPE
    rope_kernel<<<(MTOK * 64) / 256, 256>>>(q, k, pos);

    // Flash attention (fp32)
    const int flash_smem = FLASH_SMEM_FLOATS * (int)sizeof(float);
    cudaFuncSetAttribute(flash_kernel, cudaFuncAttributeMaxDynamicSharedMemorySize, flash_smem);
    flash_kernel<<<dim3(SEQ / 64, NHEADS, BATCH), 256, flash_smem>>>(q, k, v, attn);

    // Output projection
    split_kernel<<<(n16M + 255) / 256, 256>>>(attn, Ahi, Alo, n16M);
    gemm_bf16x3<<<dim3(HID / 128, MTOK / 128), 256, GEMM_SMEM>>>(Ahi, Alo, Wohi, Wolo, out, HID);
}

// round 5
// speedup vs baseline: 3.1901x; 1.5393x over previous
#include <cuda_runtime.h>
#include <cuda_bf16.h>
#include <math.h>
#include <float.h>
#include <stdint.h>

// Problem constants
#define BATCH    2
#define SEQ      2048
#define MTOK     (BATCH * SEQ)     // 4096 tokens
#define HID      4096
#define NHEADS   32
#define NKV      8
#define HDIM     128
#define KVHID    (NKV * HDIM)      // 1024
#define GK       4096              // K dim of every projection GEMM

#define LOG2E 1.4426950408889634f

// ---------------------------------------------------------------------------
// Scratch (allocation-free rule: device globals). uint4 for 16B alignment.
// ---------------------------------------------------------------------------
__device__ float g_q[(size_t)MTOK * HID];
__device__ float g_k[(size_t)MTOK * KVHID];
__device__ float g_v[(size_t)MTOK * KVHID];
__device__ float g_attn[(size_t)MTOK * HID];

#define U4(nbf16) ((nbf16) / 8)
__device__ uint4 g_Xhi [U4((size_t)MTOK * HID)];
__device__ uint4 g_Xlo [U4((size_t)MTOK * HID)];
__device__ uint4 g_Wqhi[U4((size_t)HID * HID)];
__device__ uint4 g_Wqlo[U4((size_t)HID * HID)];
__device__ uint4 g_Wkhi[U4((size_t)KVHID * HID)];
__device__ uint4 g_Wklo[U4((size_t)KVHID * HID)];
__device__ uint4 g_Wvhi[U4((size_t)KVHID * HID)];
__device__ uint4 g_Wvlo[U4((size_t)KVHID * HID)];
__device__ uint4 g_Wohi[U4((size_t)HID * HID)];
__device__ uint4 g_Wolo[U4((size_t)HID * HID)];
__device__ uint4 g_Ahi [U4((size_t)MTOK * HID)];
__device__ uint4 g_Alo [U4((size_t)MTOK * HID)];
// flash bf16 operands
__device__ uint4 g_qhi [U4((size_t)MTOK * HID)];
__device__ uint4 g_qlo [U4((size_t)MTOK * HID)];
__device__ uint4 g_khi [U4((size_t)MTOK * KVHID)];
__device__ uint4 g_klo [U4((size_t)MTOK * KVHID)];
__device__ uint4 g_vhi [U4((size_t)MTOK * KVHID)];
__device__ uint4 g_vlo [U4((size_t)MTOK * KVHID)];

// ---------------------------------------------------------------------------
// Common PTX helpers
// ---------------------------------------------------------------------------
__device__ __forceinline__ uint32_t swz(uint32_t off) {
    return off ^ ((off >> 3) & 0x70);
}
__device__ __forceinline__ uint32_t smem_u32(const void* p) {
    return (uint32_t)__cvta_generic_to_shared(p);
}
__device__ __forceinline__ void cp16(uint32_t dst, const void* src) {
    asm volatile("cp.async.cg.shared.global [%0], [%1], 16;\n" :: "r"(dst), "l"(src));
}
__device__ __forceinline__ void cp_commit() {
    asm volatile("cp.async.commit_group;\n");
}
__device__ __forceinline__ void cp_wait1() {
    asm volatile("cp.async.wait_group 1;\n");
}
__device__ __forceinline__ void cp_wait0() {
    asm volatile("cp.async.wait_group 0;\n");
}
__device__ __forceinline__ void ldsm4(uint32_t r[4], uint32_t addr) {
    asm volatile("ldmatrix.sync.aligned.m8n8.x4.shared.b16 {%0,%1,%2,%3}, [%4];\n"
        : "=r"(r[0]), "=r"(r[1]), "=r"(r[2]), "=r"(r[3]) : "r"(addr));
}
__device__ __forceinline__ void ldsm4t(uint32_t r[4], uint32_t addr) {
    asm volatile("ldmatrix.sync.aligned.m8n8.x4.trans.shared.b16 {%0,%1,%2,%3}, [%4];\n"
        : "=r"(r[0]), "=r"(r[1]), "=r"(r[2]), "=r"(r[3]) : "r"(addr));
}
__device__ __forceinline__ void mma16816(float c[4], const uint32_t a[4],
                                         uint32_t b0, uint32_t b1) {
    asm volatile(
        "mma.sync.aligned.m16n8k16.row.col.f32.bf16.bf16.f32 "
        "{%0,%1,%2,%3}, {%4,%5,%6,%7}, {%8,%9}, {%0,%1,%2,%3};\n"
        : "+f"(c[0]), "+f"(c[1]), "+f"(c[2]), "+f"(c[3])
        : "r"(a[0]), "r"(a[1]), "r"(a[2]), "r"(a[3]), "r"(b0), "r"(b1));
}

// ---------------------------------------------------------------------------
// Split fp32 -> (bf16 hi, bf16 lo)
// ---------------------------------------------------------------------------
__global__ __launch_bounds__(256) void split_kernel(
    const float* __restrict__ src, __nv_bfloat16* __restrict__ hi,
    __nv_bfloat16* __restrict__ lo, int n4)
{
    int i = blockIdx.x * blockDim.x + threadIdx.x;
    if (i >= n4) return;
    float4 v = ((const float4*)src)[i];
    __nv_bfloat16 h0 = __float2bfloat16(v.x);
    __nv_bfloat16 h1 = __float2bfloat16(v.y);
    __nv_bfloat16 h2 = __float2bfloat16(v.z);
    __nv_bfloat16 h3 = __float2bfloat16(v.w);
    __nv_bfloat162 H01; H01.x = h0; H01.y = h1;
    __nv_bfloat162 H23; H23.x = h2; H23.y = h3;
    __nv_bfloat162 L01, L23;
    L01.x = __float2bfloat16(v.x - __bfloat162float(h0));
    L01.y = __float2bfloat16(v.y - __bfloat162float(h1));
    L23.x = __float2bfloat16(v.z - __bfloat162float(h2));
    L23.y = __float2bfloat16(v.w - __bfloat162float(h3));
    ((__nv_bfloat162*)hi)[2 * i]     = H01;
    ((__nv_bfloat162*)hi)[2 * i + 1] = H23;
    ((__nv_bfloat162*)lo)[2 * i]     = L01;
    ((__nv_bfloat162*)lo)[2 * i + 1] = L23;
}

// ---------------------------------------------------------------------------
// bf16x3 tensor-core GEMM (unchanged from R4 — verified correct)
// ---------------------------------------------------------------------------
#define GEMM_STAGES 3
#define TILE_BYTES  (128 * 64 * 2)
#define GEMM_SMEM   (GEMM_STAGES * 2 * TILE_BYTES)

__global__ __launch_bounds__(256) void gemm_bf16x3(
    const __nv_bfloat16* __restrict__ Ahi, const __nv_bfloat16* __restrict__ Alo,
    const __nv_bfloat16* __restrict__ Bhi, const __nv_bfloat16* __restrict__ Blo,
    float* __restrict__ C, int N)
{
    extern __shared__ __align__(16) char dsm[];
    const uint32_t aS = smem_u32(dsm);
    const uint32_t bS = aS + GEMM_STAGES * TILE_BYTES;

    const int tid  = threadIdx.x;
    const int lane = tid & 31;
    const int wid  = tid >> 5;
    const int wm   = wid >> 2;
    const int wn   = wid & 3;
    const int bm   = blockIdx.y * 128;
    const int bn   = blockIdx.x * 128;

    const int KCHUNKS = 3 * GK / 64;

    float acc[4][4][4];
#pragma unroll
    for (int i = 0; i < 4; i++)
#pragma unroll
        for (int j = 0; j < 4; j++)
#pragma unroll
            for (int t = 0; t < 4; t++) acc[i][j][t] = 0.f;

    int lr[4], lj[4];
#pragma unroll
    for (int i = 0; i < 4; i++) {
        int lin = i * 256 + tid;
        lr[i] = lin >> 3;
        lj[i] = lin & 7;
    }

    auto issue_loads = [&](int c, int st) {
        int pass  = c >> 6;
        int kreal = (c & 63) << 6;
        const __nv_bfloat16* Asrc = (pass < 2) ? Ahi : Alo;
        const __nv_bfloat16* Bsrc = (pass == 1) ? Blo : Bhi;
#pragma unroll
        for (int i = 0; i < 4; i++) {
            uint32_t off = swz(lr[i] * 128 + lj[i] * 16);
            cp16(aS + st * TILE_BYTES + off,
                 Asrc + (size_t)(bm + lr[i]) * GK + kreal + lj[i] * 8);
            cp16(bS + st * TILE_BYTES + off,
                 Bsrc + (size_t)(bn + lr[i]) * GK + kreal + lj[i] * 8);
        }
    };

    issue_loads(0, 0); cp_commit();
    issue_loads(1, 1); cp_commit();

    for (int c = 0; c < KCHUNKS; c++) {
        cp_wait1();
        __syncthreads();

        if (c + 2 < KCHUNKS) issue_loads(c + 2, (c + 2) % GEMM_STAGES);
        cp_commit();

        const int st = c % GEMM_STAGES;
        const uint32_t aT = aS + st * TILE_BYTES;
        const uint32_t bT = bS + st * TILE_BYTES;

#pragma unroll
        for (int kk = 0; kk < 64; kk += 16) {
            uint32_t afr[4][4];
            uint32_t bfr[2][4];
#pragma unroll
            for (int mt = 0; mt < 4; mt++) {
                int row = wm * 64 + mt * 16 + (lane & 15);
                uint32_t off = row * 128 + kk * 2 + (lane >> 4) * 16;
                ldsm4(afr[mt], aT + swz(off));
            }
#pragma unroll
            for (int nt2 = 0; nt2 < 2; nt2++) {
                int row = wn * 32 + nt2 * 16 + (lane & 7) + ((lane >> 4) & 1) * 8;
                uint32_t off = row * 128 + kk * 2 + ((lane >> 3) & 1) * 16;
                ldsm4(bfr[nt2], bT + swz(off));
            }
#pragma unroll
            for (int mt = 0; mt < 4; mt++)
#pragma unroll
                for (int nt = 0; nt < 4; nt++)
                    mma16816(acc[mt][nt], afr[mt],
                             bfr[nt >> 1][(nt & 1) * 2],
                             bfr[nt >> 1][(nt & 1) * 2 + 1]);
        }
    }

#pragma unroll
    for (int mt = 0; mt < 4; mt++) {
#pragma unroll
        for (int nt = 0; nt < 4; nt++) {
            int row = bm + wm * 64 + mt * 16 + (lane >> 2);
            int col = bn + wn * 32 + nt * 8 + (lane & 3) * 2;
            float2 v0 = make_float2(acc[mt][nt][0], acc[mt][nt][1]);
            float2 v1 = make_float2(acc[mt][nt][2], acc[mt][nt][3]);
            *(float2*)&C[(size_t)row * N + col] = v0;
            *(float2*)&C[(size_t)(row + 8) * N + col] = v1;
        }
    }
}

// ---------------------------------------------------------------------------
// RoPE + split: q (scaled by 1/sqrt(d)) and k -> bf16 hi/lo pairs.
// ---------------------------------------------------------------------------
__global__ __launch_bounds__(256) void rope_split_kernel(
    const float* __restrict__ Qb, const float* __restrict__ Kb,
    __nv_bfloat16* __restrict__ qhi, __nv_bfloat16* __restrict__ qlo,
    __nv_bfloat16* __restrict__ khi, __nv_bfloat16* __restrict__ klo,
    const int* __restrict__ pos)
{
    int idx = blockIdx.x * blockDim.x + threadIdx.x;   // MTOK*64
    int token = idx >> 6;
    int j = idx & 63;
    double inv = exp(((double)(-2 * j) / 128.0) * log(10000.0));
    double ang = (double)pos[token] * inv;
    float c = (float)cos(ang);
    float s = (float)sin(ang);
    const float scale = 0.08838834764831845f;

    auto wr = [](__nv_bfloat16* hi, __nv_bfloat16* lo, size_t off, float y) {
        __nv_bfloat16 h = __float2bfloat16(y);
        hi[off] = h;
        lo[off] = __float2bfloat16(y - __bfloat162float(h));
    };

    const float* q = Qb + (size_t)token * HID;
    size_t qo = (size_t)token * HID;
#pragma unroll
    for (int h = 0; h < NHEADS; h++) {
        float x1 = q[h * HDIM + j];
        float x2 = q[h * HDIM + 64 + j];
        wr(qhi, qlo, qo + h * HDIM + j,      (x1 * c - x2 * s) * scale);
        wr(qhi, qlo, qo + h * HDIM + 64 + j, (x2 * c + x1 * s) * scale);
    }
    const float* k = Kb + (size_t)token * KVHID;
    size_t ko = (size_t)token * KVHID;
#pragma unroll
    for (int h = 0; h < NKV; h++) {
        float x1 = k[h * HDIM + j];
        float x2 = k[h * HDIM + 64 + j];
        wr(khi, klo, ko + h * HDIM + j,      x1 * c - x2 * s);
        wr(khi, klo, ko + h * HDIM + 64 + j, x2 * c + x1 * s);
    }
}

// ---------------------------------------------------------------------------
// Tensor-core flash attention, causal, GQA, bf16x3 accuracy.
// q-tile 128, kv-tile 64, 8 warps x 16 rows, 256 threads.
// smem: Qhi 32K | Qlo 32K | 2 stages x (Khi|Klo|Vhi|Vlo 16K each) = 192KB.
// K/V smem layout: chunked [row][64-col chunk of 128B] with SW128 swizzle
// (identical addressing to gemm_bf16x3, which is verified).
// ---------------------------------------------------------------------------
#define FQ  128
#define FKV 64
#define FLASH_SMEM (192 * 1024)

__global__ __launch_bounds__(256, 1) void flash_mma(
    const __nv_bfloat16* __restrict__ Qhi, const __nv_bfloat16* __restrict__ Qlo,
    const __nv_bfloat16* __restrict__ Khi, const __nv_bfloat16* __restrict__ Klo,
    const __nv_bfloat16* __restrict__ Vhi, const __nv_bfloat16* __restrict__ Vlo,
    float* __restrict__ O)
{
    extern __shared__ __align__(16) char fsm[];
    const uint32_t smBase = smem_u32(fsm);

    const int tid = threadIdx.x, lane = tid & 31, wid = tid >> 5;
    const int qt = blockIdx.x, h = blockIdx.y, b = blockIdx.z;
    const int q0 = qt * FQ;
    const int kvh = h >> 2;
    const int ntiles = (q0 + FQ) / FKV;      // 2*qt + 2
    const int rowbase = wid * 16;

    // ---- Q load: 2 tiles (hi, lo), 128 rows x 128 cols bf16, chunked+swz ----
    {
        const __nv_bfloat16* qs[2] = {
            Qhi + ((size_t)b * SEQ + q0) * HID + h * HDIM,
            Qlo + ((size_t)b * SEQ + q0) * HID + h * HDIM };
#pragma unroll
        for (int t = 0; t < 2; t++)
#pragma unroll
            for (int i = 0; i < 8; i++) {
                int u = tid + 256 * i;              // 0..2047
                int row = u >> 4, j = u & 15;
                cp16(smBase + t * 32768 + (j >> 3) * 16384 + swz(row * 128 + (j & 7) * 16),
                     qs[t] + (size_t)row * HID + j * 8);
            }
        cp_commit();
    }

    auto issue_kv = [&](int kt, int s) {
        const int k0 = kt * FKV;
        const size_t base = ((size_t)b * SEQ + k0) * KVHID + kvh * HDIM;
        const __nv_bfloat16* srcs[4] = { Khi + base, Klo + base, Vhi + base, Vlo + base };
        const uint32_t dbase = smBase + 65536 + s * 65536;
#pragma unroll
        for (int bfi = 0; bfi < 4; bfi++)
#pragma unroll
            for (int i = 0; i < 4; i++) {
                int u = tid + 256 * i;              // 0..1023
                int row = u >> 4, j = u & 15;
                cp16(dbase + bfi * 16384 + (j >> 3) * 8192 + swz(row * 128 + (j & 7) * 16),
                     srcs[bfi] + (size_t)row * KVHID + j * 8);
            }
    };

    issue_kv(0, 0); cp_commit();

    float m0 = -1e30f, m1 = -1e30f, l0 = 0.f, l1 = 0.f;
    float oacc[16][4];
#pragma unroll
    for (int i = 0; i < 16; i++)
#pragma unroll
        for (int j = 0; j < 4; j++) oacc[i][j] = 0.f;

    for (int kt = 0; kt < ntiles; kt++) {
        if (kt + 1 < ntiles) { issue_kv(kt + 1, (kt + 1) & 1); cp_commit(); cp_wait1(); }
        else                 { cp_wait0(); }
        __syncthreads();

        const int k0 = kt * FKV;
        const bool active = (k0 <= q0 + rowbase + 15);
        if (active) {
            const uint32_t kvb = smBase + 65536 + (kt & 1) * 65536;
            const uint32_t khiS = kvb, kloS = kvb + 16384;
            const uint32_t vhiS = kvb + 32768, vloS = kvb + 49152;

            // ---- S = Q K^T  (3 passes) ----
            float sacc[8][4];
#pragma unroll
            for (int i = 0; i < 8; i++)
#pragma unroll
                for (int j = 0; j < 4; j++) sacc[i][j] = 0.f;

#pragma unroll
            for (int pass = 0; pass < 3; pass++) {
                const uint32_t qb = smBase + ((pass < 2) ? 0 : 32768);
                const uint32_t kb = (pass == 1) ? kloS : khiS;
#pragma unroll
                for (int kk = 0; kk < 128; kk += 16) {
                    uint32_t af[4];
                    {
                        int row = rowbase + (lane & 15);
                        uint32_t off = (kk >> 6) * 16384 +
                            swz(row * 128 + (kk & 63) * 2 + (lane >> 4) * 16);
                        ldsm4(af, qb + off);
                    }
                    uint32_t bf[4][4];
#pragma unroll
                    for (int nt2 = 0; nt2 < 4; nt2++) {
                        int row = nt2 * 16 + (lane & 7) + ((lane >> 4) & 1) * 8;
                        uint32_t off = (kk >> 6) * 8192 +
                            swz(row * 128 + (kk & 63) * 2 + ((lane >> 3) & 1) * 16);
                        ldsm4(bf[nt2], kb + off);
                    }
#pragma unroll
                    for (int nt = 0; nt < 8; nt++)
                        mma16816(sacc[nt], af,
                                 bf[nt >> 1][(nt & 1) * 2],
                                 bf[nt >> 1][(nt & 1) * 2 + 1]);
                }
            }

            // ---- mask (diagonal tiles only) ----
            const int rg0 = q0 + rowbase + (lane >> 2);   // row of c0/c1
            if (k0 + 63 > q0 + rowbase) {
#pragma unroll
                for (int nt = 0; nt < 8; nt++) {
                    int cbase = k0 + nt * 8 + (lane & 3) * 2;
                    if (cbase     > rg0)     sacc[nt][0] = -1e30f;
                    if (cbase + 1 > rg0)     sacc[nt][1] = -1e30f;
                    if (cbase     > rg0 + 8) sacc[nt][2] = -1e30f;
                    if (cbase + 1 > rg0 + 8) sacc[nt][3] = -1e30f;
                }
            }

            // ---- online softmax in fragments ----
            float mx0 = m0, mx1 = m1;
#pragma unroll
            for (int nt = 0; nt < 8; nt++) {
                mx0 = fmaxf(mx0, fmaxf(sacc[nt][0], sacc[nt][1]));
                mx1 = fmaxf(mx1, fmaxf(sacc[nt][2], sacc[nt][3]));
            }
            mx0 = fmaxf(mx0, __shfl_xor_sync(0xffffffff, mx0, 1));
            mx0 = fmaxf(mx0, __shfl_xor_sync(0xffffffff, mx0, 2));
            mx1 = fmaxf(mx1, __shfl_xor_sync(0xffffffff, mx1, 1));
            mx1 = fmaxf(mx1, __shfl_xor_sync(0xffffffff, mx1, 2));

            const float f0 = exp2f((m0 - mx0) * LOG2E);
            const float f1 = exp2f((m1 - mx1) * LOG2E);
            m0 = mx0; m1 = mx1;

            uint32_t pahi[4][4], palo[4][4];
            float l0a = 0.f, l1a = 0.f;
#pragma unroll
            for (int nt = 0; nt < 8; nt++) {
                float p0 = exp2f((sacc[nt][0] - mx0) * LOG2E);
                float p1 = exp2f((sacc[nt][1] - mx0) * LOG2E);
                float p2 = exp2f((sacc[nt][2] - mx1) * LOG2E);
                float p3 = exp2f((sacc[nt][3] - mx1) * LOG2E);
                l0a += p0 + p1; l1a += p2 + p3;
                int kt2 = nt >> 1, odd = nt & 1;
                __nv_bfloat162 h01 = __floats2bfloat162_rn(p0, p1);
                __nv_bfloat162 h23 = __floats2bfloat162_rn(p2, p3);
                __nv_bfloat162 lo01 = __floats2bfloat162_rn(
                    p0 - __bfloat162float(h01.x), p1 - __bfloat162float(h01.y));
                __nv_bfloat162 lo23 = __floats2bfloat162_rn(
                    p2 - __bfloat162float(h23.x), p3 - __bfloat162float(h23.y));
                pahi[kt2][odd * 2]     = *(uint32_t*)&h01;
                pahi[kt2][odd * 2 + 1] = *(uint32_t*)&h23;
                palo[kt2][odd * 2]     = *(uint32_t*)&lo01;
                palo[kt2][odd * 2 + 1] = *(uint32_t*)&lo23;
            }
            l0a += __shfl_xor_sync(0xffffffff, l0a, 1);
            l0a += __shfl_xor_sync(0xffffffff, l0a, 2);
            l1a += __shfl_xor_sync(0xffffffff, l1a, 1);
            l1a += __shfl_xor_sync(0xffffffff, l1a, 2);
            l0 = l0 * f0 + l0a;
            l1 = l1 * f1 + l1a;

#pragma unroll
            for (int nt = 0; nt < 16; nt++) {
                oacc[nt][0] *= f0; oacc[nt][1] *= f0;
                oacc[nt][2] *= f1; oacc[nt][3] *= f1;
            }

            // ---- O += P V  (3 passes: phi*vhi, phi*vlo, plo*vhi) ----
#pragma unroll
            for (int pass = 0; pass < 3; pass++) {
                const uint32_t (*pa)[4] = (pass == 2) ? palo : pahi;
                const uint32_t vb = (pass == 1) ? vloS : vhiS;
#pragma unroll
                for (int kt2 = 0; kt2 < 4; kt2++) {
#pragma unroll
                    for (int nt16 = 0; nt16 < 8; nt16++) {
                        uint32_t vf[4];
                        int kv = kt2 * 16 + (lane & 15);
                        int d  = nt16 * 16 + (lane >> 4) * 8;
                        uint32_t off = (d >> 6) * 8192 + swz(kv * 128 + (d & 63) * 2);
                        ldsm4t(vf, vb + off);
                        mma16816(oacc[nt16 * 2],     pa[kt2], vf[0], vf[1]);
                        mma16816(oacc[nt16 * 2 + 1], pa[kt2], vf[2], vf[3]);
                    }
                }
            }
        }
        __syncthreads();
    }

    // ---- epilogue ----
    const float il0 = 1.f / l0, il1 = 1.f / l1;
    float* ob = O + ((size_t)b * SEQ + q0 + rowbase + (lane >> 2)) * HID + h * HDIM;
#pragma unroll
    for (int nt = 0; nt < 16; nt++) {
        int d = nt * 8 + (lane & 3) * 2;
        *(float2*)&ob[d]           = make_float2(oacc[nt][0] * il0, oacc[nt][1] * il0);
        *(float2*)&ob[8 * HID + d] = make_float2(oacc[nt][2] * il1, oacc[nt][3] * il1);
    }
}

// ---------------------------------------------------------------------------
// Launch
// ---------------------------------------------------------------------------
extern "C" void kernel_launch(void* const* d_in, const int* in_sizes, int n_in,
                              void* d_out, int out_size)
{
    const float* X   = (const float*)d_in[0];
    const int*   pos = (const int*)d_in[1];
    const float* Wq  = (const float*)d_in[2];
    const float* Wk  = (const float*)d_in[3];
    const float* Wv  = (const float*)d_in[4];
    const float* Wo  = (const float*)d_in[5];
    float* out = (float*)d_out;

    float *q, *k, *v, *attn;
    cudaGetSymbolAddress((void**)&q,    g_q);
    cudaGetSymbolAddress((void**)&k,    g_k);
    cudaGetSymbolAddress((void**)&v,    g_v);
    cudaGetSymbolAddress((void**)&attn, g_attn);

    __nv_bfloat16 *Xhi, *Xlo, *Wqhi, *Wqlo, *Wkhi, *Wklo, *Wvhi, *Wvlo, *Wohi, *Wolo, *Ahi, *Alo;
    __nv_bfloat16 *qhi, *qlo, *khi, *klo, *vhi, *vlo;
    cudaGetSymbolAddress((void**)&Xhi,  g_Xhi);  cudaGetSymbolAddress((void**)&Xlo,  g_Xlo);
    cudaGetSymbolAddress((void**)&Wqhi, g_Wqhi); cudaGetSymbolAddress((void**)&Wqlo, g_Wqlo);
    cudaGetSymbolAddress((void**)&Wkhi, g_Wkhi); cudaGetSymbolAddress((void**)&Wklo, g_Wklo);
    cudaGetSymbolAddress((void**)&Wvhi, g_Wvhi); cudaGetSymbolAddress((void**)&Wvlo, g_Wvlo);
    cudaGetSymbolAddress((void**)&Wohi, g_Wohi); cudaGetSymbolAddress((void**)&Wolo, g_Wolo);
    cudaGetSymbolAddress((void**)&Ahi,  g_Ahi);  cudaGetSymbolAddress((void**)&Alo,  g_Alo);
    cudaGetSymbolAddress((void**)&qhi,  g_qhi);  cudaGetSymbolAddress((void**)&qlo,  g_qlo);
    cudaGetSymbolAddress((void**)&khi,  g_khi);  cudaGetSymbolAddress((void**)&klo,  g_klo);
    cudaGetSymbolAddress((void**)&vhi,  g_vhi);  cudaGetSymbolAddress((void**)&vlo,  g_vlo);

    const int n16M = MTOK * HID / 4;
    const int n4M  = MTOK * KVHID / 4;
    const int n16W = HID * HID / 4;
    const int n4W  = KVHID * HID / 4;

    // Splits of inputs
    split_kernel<<<(n16M + 255) / 256, 256>>>(X,  Xhi,  Xlo,  n16M);
    split_kernel<<<(n16W + 255) / 256, 256>>>(Wq, Wqhi, Wqlo, n16W);
    split_kernel<<<(n4W  + 255) / 256, 256>>>(Wk, Wkhi, Wklo, n4W);
    split_kernel<<<(n4W  + 255) / 256, 256>>>(Wv, Wvhi, Wvlo, n4W);
    split_kernel<<<(n16W + 255) / 256, 256>>>(Wo, Wohi, Wolo, n16W);

    // Projections (tensor core, bf16x3)
    cudaFuncSetAttribute(gemm_bf16x3, cudaFuncAttributeMaxDynamicSharedMemorySize, GEMM_SMEM);
    gemm_bf16x3<<<dim3(HID / 128,   MTOK / 128), 256, GEMM_SMEM>>>(Xhi, Xlo, Wqhi, Wqlo, q, HID);
    gemm_bf16x3<<<dim3(KVHID / 128, MTOK / 128), 256, GEMM_SMEM>>>(Xhi, Xlo, Wkhi, Wklo, k, KVHID);
    gemm_bf16x3<<<dim3(KVHID / 128, MTOK / 128), 256, GEMM_SMEM>>>(Xhi, Xlo, Wvhi, Wvlo, v, KVHID);

    // RoPE (+scale) and splits for flash operands
    rope_split_kernel<<<(MTOK * 64) / 256, 256>>>(q, k, qhi, qlo, khi, klo, pos);
    split_kernel<<<(n4M + 255) / 256, 256>>>(v, vhi, vlo, n4M);

    // Tensor-core flash attention
    cudaFuncSetAttribute(flash_mma, cudaFuncAttributeMaxDynamicSharedMemorySize, FLASH_SMEM);
    flash_mma<<<dim3(SEQ / FQ, NHEADS, BATCH), 256, FLASH_SMEM>>>(
        qhi, qlo, khi, klo, vhi, vlo, attn);

    // Output projection
    split_kernel<<<(n16M + 255) / 256, 256>>>(attn, Ahi, Alo, n16M);
    gemm_bf16x3<<<dim3(HID / 128, MTOK / 128), 256, GEMM_SMEM>>>(Ahi, Alo, Wohi, Wolo, out, HID);
}